// round 12
// baseline (speedup 1.0000x reference)
#include <cuda_runtime.h>
#include <cuda_bf16.h>
#include <math.h>

#define N_NODES 100000
#define N_EDGES 800000
#define E_TOT   900000   // edges + self loops
#define NH 128
#define NC 2
#define NG 16

// ---------------- scratch (device globals; no allocation) ----------------
__device__ int   g_is64;
__device__ int   g_total;               // bump allocator for CSR segments
__device__ int   g_cnt_hist[N_NODES];   // degree (incl. self loop)
__device__ int   g_ptr[N_NODES];        // CSR segment start
__device__ int   g_cursor[N_NODES];
__device__ float g_dinv[N_NODES];
__device__ uint2 g_epack[E_TOT];        // {src row, dinv[src] bits} per CSR slot
__device__ int   g_batch[N_NODES];
__device__ __nv_bfloat16 g_xbf[(size_t)N_NODES * NH];  // x in bf16
__device__ unsigned g_w1bf[64 * 128];   // W1 packed bf16x2 along k (k2 x n)
__device__ unsigned g_aggbf[(size_t)N_NODES * 64];     // Ax in bf16x2 (64 words/row)
__device__ float g_t[N_NODES * NC];     // h@W2
__device__ float g_pool[NG * NC];
__device__ float g_gcnt[NG];

// ---------------- helpers ----------------
__device__ __forceinline__ void mma_bf16(float* d, unsigned a0, unsigned a1,
                                         unsigned a2, unsigned a3,
                                         unsigned b0, unsigned b1) {
    asm volatile(
        "mma.sync.aligned.m16n8k16.row.col.f32.bf16.bf16.f32 "
        "{%0,%1,%2,%3}, {%4,%5,%6,%7}, {%8,%9}, {%0,%1,%2,%3};"
        : "+f"(d[0]), "+f"(d[1]), "+f"(d[2]), "+f"(d[3])
        : "r"(a0), "r"(a1), "r"(a2), "r"(a3), "r"(b0), "r"(b1));
}

__device__ __forceinline__ int warp_incl_scan(int v, int lane) {
#pragma unroll
    for (int off = 1; off < 32; off <<= 1) {
        int t = __shfl_up_sync(0xffffffffu, v, off);
        if (lane >= off) v += t;
    }
    return v;
}

__device__ __forceinline__ unsigned pack_bf16x2(float a, float b) {
    __nv_bfloat162 p = __float22bfloat162_rn(make_float2(a, b));
    return *(unsigned*)&p;
}

// ---------------- kernels ----------------

__global__ void k_detect(const unsigned int* __restrict__ e) {
    int lane = threadIdx.x;
    unsigned v = 0;
#pragma unroll
    for (int i = 0; i < 8; i++) v |= e[2 * (lane + 32 * i) + 1];
    int any = __any_sync(0xffffffffu, v != 0u);
    if (lane == 0) { g_is64 = !any; g_total = 0; }
}

// fused: x->bf16, W1->bf16x2 pack, zero scratch, batch convert
__global__ void k_prep(const float* __restrict__ x, const void* __restrict__ bp,
                       const float* __restrict__ W1) {
    int i = blockIdx.x * blockDim.x + threadIdx.x;
    size_t base = (size_t)i * 4;
    if (base < (size_t)N_NODES * NH) {
        float4 v = *(const float4*)&x[base];
        unsigned u0 = pack_bf16x2(v.x, v.y);
        unsigned u1 = pack_bf16x2(v.z, v.w);
        *(uint2*)&g_xbf[base] = make_uint2(u0, u1);
    }
    if (i < 64 * 128) {
        int k2 = i >> 7, n = i & 127;
        g_w1bf[i] = pack_bf16x2(W1[(2 * k2) * 128 + n], W1[(2 * k2 + 1) * 128 + n]);
    }
    if (i < N_NODES) {
        g_cnt_hist[i] = 0;
        g_batch[i] = g_is64 ? (int)((const long long*)bp)[i] : ((const int*)bp)[i];
    }
    if (i < NG * NC) g_pool[i] = 0.f;
    if (i < NG)      g_gcnt[i] = 0.f;
}

// histogram of target nodes (edges + implicit self loops)
__global__ void k_build(const void* __restrict__ ep) {
    int e = blockIdx.x * blockDim.x + threadIdx.x;
    if (e >= E_TOT) return;
    int c;
    if (e < N_EDGES) {
        c = g_is64 ? (int)((const long long*)ep)[N_EDGES + e]
                   : ((const int*)ep)[N_EDGES + e];
    } else {
        c = e - N_EDGES;  // self loop
    }
    atomicAdd(&g_cnt_hist[c], 1);
}

// segment allocation via warp-aggregated bump allocator (order-free CSR)
__global__ void k_alloc() {
    int i = blockIdx.x * blockDim.x + threadIdx.x;
    int lane = threadIdx.x & 31;
    int v = (i < N_NODES) ? g_cnt_hist[i] : 0;
    int s = warp_incl_scan(v, lane);                 // inclusive
    int base = 0;
    if (lane == 31) base = atomicAdd(&g_total, s);
    base = __shfl_sync(0xffffffffu, base, 31);
    if (i < N_NODES) {
        int p = base + s - v;                        // exclusive within warp
        g_ptr[i] = p;
        g_cursor[i] = p;
        float d = (float)v;
        g_dinv[i] = (d > 0.f) ? rsqrtf(d) : 0.f;
    }
}

// fill CSR with packed {src, dinv[src]} records (re-decode edge_index)
__global__ void k_fill(const void* __restrict__ ep) {
    int e = blockIdx.x * blockDim.x + threadIdx.x;
    if (e >= E_TOT) return;
    int r, c;
    if (e < N_EDGES) {
        if (g_is64) { const long long* p = (const long long*)ep; r = (int)p[e]; c = (int)p[N_EDGES + e]; }
        else        { const int*       p = (const int*)ep;       r = p[e];      c = p[N_EDGES + e]; }
    } else {
        r = c = e - N_EDGES;
    }
    float w = g_dinv[r];
    int slot = atomicAdd(&g_cursor[c], 1);
    g_epack[slot] = make_uint2((unsigned)r, __float_as_uint(w));
}

// ---------------------------------------------------------------------------
// agg = Â x (bf16): HALF-WARP (16 lanes) per node, uint4 row loads.
// ---------------------------------------------------------------------------
__global__ void k_agg1() {
    int gt = blockIdx.x * blockDim.x + threadIdx.x;
    int node = gt >> 4;          // 16 lanes per node
    int l = gt & 15;
    if (node >= N_NODES) return;
    int start = g_ptr[node];
    int deg = g_cnt_hist[node];
    float dc = g_dinv[node];
    float acc[8];
#pragma unroll
    for (int q = 0; q < 8; q++) acc[q] = 0.f;

    int j = 0;
    for (; j + 4 <= deg; j += 4) {
        uint2 e0 = g_epack[start + j];
        uint2 e1 = g_epack[start + j + 1];
        uint2 e2 = g_epack[start + j + 2];
        uint2 e3 = g_epack[start + j + 3];
        uint4 u0 = *((const uint4*)&g_xbf[(size_t)e0.x * NH] + l);
        uint4 u1 = *((const uint4*)&g_xbf[(size_t)e1.x * NH] + l);
        uint4 u2 = *((const uint4*)&g_xbf[(size_t)e2.x * NH] + l);
        uint4 u3 = *((const uint4*)&g_xbf[(size_t)e3.x * NH] + l);
        float w0 = __uint_as_float(e0.y), w1 = __uint_as_float(e1.y);
        float w2 = __uint_as_float(e2.y), w3 = __uint_as_float(e3.y);
        const unsigned* p0 = &u0.x; const unsigned* p1 = &u1.x;
        const unsigned* p2 = &u2.x; const unsigned* p3 = &u3.x;
#pragma unroll
        for (int q = 0; q < 4; q++) {
            float2 f0 = __bfloat1622float2(*(__nv_bfloat162*)&p0[q]);
            float2 f1 = __bfloat1622float2(*(__nv_bfloat162*)&p1[q]);
            float2 f2 = __bfloat1622float2(*(__nv_bfloat162*)&p2[q]);
            float2 f3 = __bfloat1622float2(*(__nv_bfloat162*)&p3[q]);
            acc[2*q+0] += w0 * f0.x + w1 * f1.x + w2 * f2.x + w3 * f3.x;
            acc[2*q+1] += w0 * f0.y + w1 * f1.y + w2 * f2.y + w3 * f3.y;
        }
    }
    for (; j < deg; j++) {
        uint2 e0 = g_epack[start + j];
        uint4 u0 = *((const uint4*)&g_xbf[(size_t)e0.x * NH] + l);
        float w0 = __uint_as_float(e0.y);
        const unsigned* p0 = &u0.x;
#pragma unroll
        for (int q = 0; q < 4; q++) {
            float2 f0 = __bfloat1622float2(*(__nv_bfloat162*)&p0[q]);
            acc[2*q+0] += w0 * f0.x;
            acc[2*q+1] += w0 * f0.y;
        }
    }
#pragma unroll
    for (int q = 0; q < 8; q++) acc[q] *= dc;
    uint4 o;
    o.x = pack_bf16x2(acc[0], acc[1]);
    o.y = pack_bf16x2(acc[2], acc[3]);
    o.z = pack_bf16x2(acc[4], acc[5]);
    o.w = pack_bf16x2(acc[6], acc[7]);
    *((uint4*)&g_aggbf[(size_t)node * 64] + l) = o;
}

// ---------------------------------------------------------------------------
// Dense bf16 GEMM: h = relu(agg @ W1 + b1); t = h @ W2 fused in registers.
// Two n-half warps hold partial W2 projections; combined via smem.
// ---------------------------------------------------------------------------
__global__ __launch_bounds__(256, 3) void k_gemm(const float* __restrict__ b1,
                                                 const float* __restrict__ W2) {
    __shared__ unsigned As2[64][68];    // 64 rows x 64 k2-words (+pad)
    __shared__ unsigned Ws2[64][136];   // full W1: 64 k2 x 128 n (+pad)
    __shared__ float W2s[NH * NC];
    __shared__ float b1s[NH];
    __shared__ float tsh[2][64][2];     // per-n-half partial t

    int tid = threadIdx.x, wid = tid >> 5, lane = tid & 31;
    int row0 = blockIdx.x * 64;

    if (tid < NH) b1s[tid] = b1[tid];
    W2s[tid] = W2[tid];

#pragma unroll
    for (int t = 0; t < 8; t++) {
        int u4 = tid + t * 256;
        int k2 = u4 >> 5, n4 = u4 & 31;
        *(uint4*)&Ws2[k2][n4 * 4] = ((const uint4*)&g_w1bf[k2 * 128])[n4];
    }
#pragma unroll
    for (int t = 0; t < 4; t++) {
        int u4 = tid + t * 256;
        int r = u4 >> 4, c4 = u4 & 15;
        uint4 v = make_uint4(0u, 0u, 0u, 0u);
        if (row0 + r < N_NODES)
            v = ((const uint4*)&g_aggbf[(size_t)(row0 + r) * 64])[c4];
        *(uint4*)&As2[r][c4 * 4] = v;
    }
    __syncthreads();

    int wm = wid >> 1, wn = wid & 1;
    int g = lane >> 2, t4 = lane & 3;
    float acc[8][4];
#pragma unroll
    for (int t = 0; t < 8; t++)
#pragma unroll
        for (int j = 0; j < 4; j++) acc[t][j] = 0.f;

#pragma unroll
    for (int chunk = 0; chunk < 8; chunk++) {
        unsigned a0 = As2[wm * 16 + g][chunk * 8 + t4];
        unsigned a1 = As2[wm * 16 + g + 8][chunk * 8 + t4];
        unsigned a2 = As2[wm * 16 + g][chunk * 8 + t4 + 4];
        unsigned a3 = As2[wm * 16 + g + 8][chunk * 8 + t4 + 4];
#pragma unroll
        for (int tile = 0; tile < 8; tile++) {
            int n0 = wn * 64 + tile * 8;
            unsigned b0 = Ws2[chunk * 8 + t4][n0 + g];
            unsigned bb = Ws2[chunk * 8 + t4 + 4][n0 + g];
            mma_bf16(acc[tile], a0, a1, a2, a3, b0, bb);
        }
    }

    float tA0 = 0.f, tA1 = 0.f, tB0 = 0.f, tB1 = 0.f;
#pragma unroll
    for (int tile = 0; tile < 8; tile++) {
        int c0 = wn * 64 + tile * 8 + t4 * 2;
        float bias0 = b1s[c0], bias1 = b1s[c0 + 1];
        float h00 = fmaxf(acc[tile][0] + bias0, 0.f);
        float h01 = fmaxf(acc[tile][1] + bias1, 0.f);
        float h10 = fmaxf(acc[tile][2] + bias0, 0.f);
        float h11 = fmaxf(acc[tile][3] + bias1, 0.f);
        float w00 = W2s[c0 * 2 + 0], w01 = W2s[c0 * 2 + 1];
        float w10 = W2s[(c0 + 1) * 2 + 0], w11 = W2s[(c0 + 1) * 2 + 1];
        tA0 += h00 * w00 + h01 * w10;
        tA1 += h00 * w01 + h01 * w11;
        tB0 += h10 * w00 + h11 * w10;
        tB1 += h10 * w01 + h11 * w11;
    }
    tA0 += __shfl_xor_sync(0xffffffffu, tA0, 1); tA0 += __shfl_xor_sync(0xffffffffu, tA0, 2);
    tA1 += __shfl_xor_sync(0xffffffffu, tA1, 1); tA1 += __shfl_xor_sync(0xffffffffu, tA1, 2);
    tB0 += __shfl_xor_sync(0xffffffffu, tB0, 1); tB0 += __shfl_xor_sync(0xffffffffu, tB0, 2);
    tB1 += __shfl_xor_sync(0xffffffffu, tB1, 1); tB1 += __shfl_xor_sync(0xffffffffu, tB1, 2);
    if (t4 == 0) {
        int rlA = wm * 16 + g;
        int rlB = rlA + 8;
        tsh[wn][rlA][0] = tA0; tsh[wn][rlA][1] = tA1;
        tsh[wn][rlB][0] = tB0; tsh[wn][rlB][1] = tB1;
    }
    __syncthreads();
    if (tid < 128) {
        int rl = tid >> 1, c = tid & 1;
        int gr = row0 + rl;
        if (gr < N_NODES)
            g_t[gr * 2 + c] = tsh[0][rl][c] + tsh[1][rl][c];
    }
}

// layer-2 aggregation (CSR, no atomics) fused with mean-pool accumulation
__global__ void k_agg2_pool(const float* __restrict__ b2) {
    __shared__ float sp[NG * NC];
    __shared__ float sc[NG];
    int tid = threadIdx.x;
    if (tid < NG * NC) sp[tid] = 0.f;
    if (tid < NG)      sc[tid] = 0.f;
    __syncthreads();
    int i = blockIdx.x * blockDim.x + tid;
    if (i < N_NODES) {
        int start = g_ptr[i];
        int deg = g_cnt_hist[i];
        float a0 = 0.f, a1 = 0.f;
        int j = 0;
        for (; j + 2 <= deg; j += 2) {
            uint2 e0 = g_epack[start + j];
            uint2 e1 = g_epack[start + j + 1];
            float w0 = __uint_as_float(e0.y), w1 = __uint_as_float(e1.y);
            float2 v0 = *(const float2*)&g_t[e0.x * 2];
            float2 v1 = *(const float2*)&g_t[e1.x * 2];
            a0 += w0 * v0.x + w1 * v1.x;
            a1 += w0 * v0.y + w1 * v1.y;
        }
        if (j < deg) {
            uint2 e0 = g_epack[start + j];
            float w0 = __uint_as_float(e0.y);
            float2 v0 = *(const float2*)&g_t[e0.x * 2];
            a0 += w0 * v0.x; a1 += w0 * v0.y;
        }
        float dc = g_dinv[i];
        a0 = a0 * dc + b2[0];
        a1 = a1 * dc + b2[1];
        int b = g_batch[i];
        atomicAdd(&sp[b * 2 + 0], a0);
        atomicAdd(&sp[b * 2 + 1], a1);
        atomicAdd(&sc[b], 1.f);
    }
    __syncthreads();
    if (tid < NG * NC && sp[tid] != 0.f) atomicAdd(&g_pool[tid], sp[tid]);
    if (tid < NG && sc[tid] != 0.f)      atomicAdd(&g_gcnt[tid], sc[tid]);
}

__global__ void k_final(float* __restrict__ out) {
    int g = threadIdx.x;
    if (g >= NG) return;
    float cnt = g_gcnt[g];
    float m = fmaxf(cnt, 1.0f);
    float p0 = g_pool[g * 2 + 0] / m;
    float p1 = g_pool[g * 2 + 1] / m;
    float mx = fmaxf(p0, p1);
    float lse = mx + logf(expf(p0 - mx) + expf(p1 - mx));
    out[g * 2 + 0] = p0 - lse;
    out[g * 2 + 1] = p1 - lse;
}

// ---------------- launch ----------------
extern "C" void kernel_launch(void* const* d_in, const int* in_sizes, int n_in,
                              void* d_out, int out_size) {
    const float* x     = (const float*)d_in[0];
    const void*  ei    = d_in[1];
    const void*  batch = d_in[2];
    const float* W1    = (const float*)d_in[3];
    const float* b1    = (const float*)d_in[4];
    const float* W2    = (const float*)d_in[5];
    const float* b2    = (const float*)d_in[6];
    float* out = (float*)d_out;

    k_detect<<<1, 32>>>((const unsigned int*)ei);
    k_prep<<<((N_NODES * NH / 4) + 255) / 256, 256>>>(x, batch, W1);
    k_build<<<(E_TOT + 255) / 256, 256>>>(ei);
    k_alloc<<<(N_NODES + 255) / 256, 256>>>();
    k_fill<<<(E_TOT + 255) / 256, 256>>>(ei);
    k_agg1<<<(N_NODES * 16 + 255) / 256, 256>>>();
    k_gemm<<<(N_NODES + 63) / 64, 256>>>(b1, W2);
    k_agg2_pool<<<(N_NODES + 255) / 256, 256>>>(b2);
    k_final<<<1, 32>>>(out);
}

// round 15
// speedup vs baseline: 1.0538x; 1.0538x over previous
#include <cuda_runtime.h>
#include <cuda_bf16.h>
#include <math.h>

#define N_NODES 100000
#define N_EDGES 800000
#define E_TOT   900000   // edges + self loops
#define NH 128
#define NC 2
#define NG 16

// ---------------- scratch (device globals; no allocation) ----------------
__device__ int   g_is64;
__device__ int   g_total;               // bump allocator for CSR segments
__device__ int   g_done;                // last-block ticket for fused final
__device__ int   g_cnt_hist[N_NODES];   // degree (incl. self loop)
__device__ int   g_ptr[N_NODES];        // CSR segment start
__device__ int   g_cursor[N_NODES];
__device__ float g_dinv[N_NODES];
__device__ uint2 g_epack[E_TOT];        // {src row, dinv[src] bits} per CSR slot
__device__ int   g_batch[N_NODES];
__device__ __nv_bfloat16 g_xbf[(size_t)N_NODES * NH];  // x in bf16
__device__ unsigned g_w1bf[64 * 128];   // W1 packed bf16x2 along k (k2 x n)
__device__ unsigned g_aggbf[(size_t)N_NODES * 64];     // Ax in bf16x2 (64 words/row)
__device__ float g_t[N_NODES * NC];     // h@W2
__device__ float g_pool[NG * NC];
__device__ float g_gcnt[NG];

// ---------------- helpers ----------------
__device__ __forceinline__ void mma_bf16(float* d, unsigned a0, unsigned a1,
                                         unsigned a2, unsigned a3,
                                         unsigned b0, unsigned b1) {
    asm volatile(
        "mma.sync.aligned.m16n8k16.row.col.f32.bf16.bf16.f32 "
        "{%0,%1,%2,%3}, {%4,%5,%6,%7}, {%8,%9}, {%0,%1,%2,%3};"
        : "+f"(d[0]), "+f"(d[1]), "+f"(d[2]), "+f"(d[3])
        : "r"(a0), "r"(a1), "r"(a2), "r"(a3), "r"(b0), "r"(b1));
}

__device__ __forceinline__ int warp_incl_scan(int v, int lane) {
#pragma unroll
    for (int off = 1; off < 32; off <<= 1) {
        int t = __shfl_up_sync(0xffffffffu, v, off);
        if (lane >= off) v += t;
    }
    return v;
}

__device__ __forceinline__ unsigned pack_bf16x2(float a, float b) {
    __nv_bfloat162 p = __float22bfloat162_rn(make_float2(a, b));
    return *(unsigned*)&p;
}

// ---------------- kernels ----------------

// fused: dtype detect (block 0 warp 0), x->bf16, W1->bf16x2, zero scratch
__global__ void k_prep(const float* __restrict__ x, const float* __restrict__ W1,
                       const unsigned int* __restrict__ e) {
    int i = blockIdx.x * blockDim.x + threadIdx.x;
    if (blockIdx.x == 0 && threadIdx.x < 32) {
        int lane = threadIdx.x;
        unsigned v = 0;
#pragma unroll
        for (int q = 0; q < 8; q++) v |= e[2 * (lane + 32 * q) + 1];
        int any = __any_sync(0xffffffffu, v != 0u);
        if (lane == 0) { g_is64 = !any; g_total = 0; g_done = 0; }
    }
    size_t base = (size_t)i * 4;
    if (base < (size_t)N_NODES * NH) {
        float4 v = *(const float4*)&x[base];
        unsigned u0 = pack_bf16x2(v.x, v.y);
        unsigned u1 = pack_bf16x2(v.z, v.w);
        *(uint2*)&g_xbf[base] = make_uint2(u0, u1);
    }
    if (i < 64 * 128) {
        int k2 = i >> 7, n = i & 127;
        g_w1bf[i] = pack_bf16x2(W1[(2 * k2) * 128 + n], W1[(2 * k2 + 1) * 128 + n]);
    }
    if (i < N_NODES) g_cnt_hist[i] = 0;
    if (i < NG * NC) g_pool[i] = 0.f;
    if (i < NG)      g_gcnt[i] = 0.f;
}

// histogram of target nodes (edges + implicit self loops)
__global__ void k_build(const void* __restrict__ ep) {
    int e = blockIdx.x * blockDim.x + threadIdx.x;
    if (e >= E_TOT) return;
    int c;
    if (e < N_EDGES) {
        c = g_is64 ? (int)((const long long*)ep)[N_EDGES + e]
                   : ((const int*)ep)[N_EDGES + e];
    } else {
        c = e - N_EDGES;  // self loop
    }
    atomicAdd(&g_cnt_hist[c], 1);
}

// segment allocation via warp-aggregated bump allocator + batch id convert
__global__ void k_alloc(const void* __restrict__ bp) {
    int i = blockIdx.x * blockDim.x + threadIdx.x;
    int lane = threadIdx.x & 31;
    int v = (i < N_NODES) ? g_cnt_hist[i] : 0;
    int s = warp_incl_scan(v, lane);                 // inclusive
    int base = 0;
    if (lane == 31) base = atomicAdd(&g_total, s);
    base = __shfl_sync(0xffffffffu, base, 31);
    if (i < N_NODES) {
        int p = base + s - v;                        // exclusive within warp
        g_ptr[i] = p;
        g_cursor[i] = p;
        float d = (float)v;
        g_dinv[i] = (d > 0.f) ? rsqrtf(d) : 0.f;
        g_batch[i] = g_is64 ? (int)((const long long*)bp)[i] : ((const int*)bp)[i];
    }
}

// fill CSR with packed {src, dinv[src]} records (re-decode edge_index)
__global__ void k_fill(const void* __restrict__ ep) {
    int e = blockIdx.x * blockDim.x + threadIdx.x;
    if (e >= E_TOT) return;
    int r, c;
    if (e < N_EDGES) {
        if (g_is64) { const long long* p = (const long long*)ep; r = (int)p[e]; c = (int)p[N_EDGES + e]; }
        else        { const int*       p = (const int*)ep;       r = p[e];      c = p[N_EDGES + e]; }
    } else {
        r = c = e - N_EDGES;
    }
    float w = g_dinv[r];
    int slot = atomicAdd(&g_cursor[c], 1);
    g_epack[slot] = make_uint2((unsigned)r, __float_as_uint(w));
}

// ---------------------------------------------------------------------------
// agg = Â x (bf16): warp per node (uniform work per warp), 4-deep edge unroll.
// ---------------------------------------------------------------------------
__global__ void k_agg1() {
    int gt = blockIdx.x * blockDim.x + threadIdx.x;
    int w = gt >> 5, lane = gt & 31;
    if (w >= N_NODES) return;
    int start = g_ptr[w];
    int deg = g_cnt_hist[w];
    float dc = g_dinv[w];
    float4 acc = make_float4(0.f, 0.f, 0.f, 0.f);
    int j = 0;
    for (; j + 4 <= deg; j += 4) {
        uint2 e0 = g_epack[start + j];
        uint2 e1 = g_epack[start + j + 1];
        uint2 e2 = g_epack[start + j + 2];
        uint2 e3 = g_epack[start + j + 3];
        float w0 = __uint_as_float(e0.y), w1 = __uint_as_float(e1.y);
        float w2 = __uint_as_float(e2.y), w3 = __uint_as_float(e3.y);
        uint2 u0 = *((const uint2*)&g_xbf[(size_t)e0.x * NH] + lane);
        uint2 u1 = *((const uint2*)&g_xbf[(size_t)e1.x * NH] + lane);
        uint2 u2 = *((const uint2*)&g_xbf[(size_t)e2.x * NH] + lane);
        uint2 u3 = *((const uint2*)&g_xbf[(size_t)e3.x * NH] + lane);
        float2 a0 = __bfloat1622float2(*(__nv_bfloat162*)&u0.x);
        float2 b0 = __bfloat1622float2(*(__nv_bfloat162*)&u0.y);
        float2 a1 = __bfloat1622float2(*(__nv_bfloat162*)&u1.x);
        float2 b1 = __bfloat1622float2(*(__nv_bfloat162*)&u1.y);
        float2 a2 = __bfloat1622float2(*(__nv_bfloat162*)&u2.x);
        float2 b2 = __bfloat1622float2(*(__nv_bfloat162*)&u2.y);
        float2 a3 = __bfloat1622float2(*(__nv_bfloat162*)&u3.x);
        float2 b3 = __bfloat1622float2(*(__nv_bfloat162*)&u3.y);
        acc.x += w0 * a0.x + w1 * a1.x + w2 * a2.x + w3 * a3.x;
        acc.y += w0 * a0.y + w1 * a1.y + w2 * a2.y + w3 * a3.y;
        acc.z += w0 * b0.x + w1 * b1.x + w2 * b2.x + w3 * b3.x;
        acc.w += w0 * b0.y + w1 * b1.y + w2 * b2.y + w3 * b3.y;
    }
    for (; j < deg; j++) {
        uint2 e0 = g_epack[start + j];
        float w0 = __uint_as_float(e0.y);
        uint2 u0 = *((const uint2*)&g_xbf[(size_t)e0.x * NH] + lane);
        float2 a0 = __bfloat1622float2(*(__nv_bfloat162*)&u0.x);
        float2 b0 = __bfloat1622float2(*(__nv_bfloat162*)&u0.y);
        acc.x += w0 * a0.x; acc.y += w0 * a0.y;
        acc.z += w0 * b0.x; acc.w += w0 * b0.y;
    }
    acc.x *= dc; acc.y *= dc; acc.z *= dc; acc.w *= dc;
    unsigned p0 = pack_bf16x2(acc.x, acc.y);
    unsigned p1 = pack_bf16x2(acc.z, acc.w);
    *(uint2*)&g_aggbf[(size_t)w * 64 + lane * 2] = make_uint2(p0, p1);
}

// ---------------------------------------------------------------------------
// Dense bf16 GEMM: h = relu(agg @ W1 + b1); t = h @ W2 fused in registers.
// Two n-half warps hold partial W2 projections; combined via smem.
// ---------------------------------------------------------------------------
__global__ __launch_bounds__(256, 3) void k_gemm(const float* __restrict__ b1,
                                                 const float* __restrict__ W2) {
    __shared__ unsigned As2[64][68];    // 64 rows x 64 k2-words (+pad)
    __shared__ unsigned Ws2[64][136];   // full W1: 64 k2 x 128 n (+pad)
    __shared__ float W2s[NH * NC];
    __shared__ float b1s[NH];
    __shared__ float tsh[2][64][2];     // per-n-half partial t

    int tid = threadIdx.x, wid = tid >> 5, lane = tid & 31;
    int row0 = blockIdx.x * 64;

    if (tid < NH) b1s[tid] = b1[tid];
    W2s[tid] = W2[tid];

#pragma unroll
    for (int t = 0; t < 8; t++) {
        int u4 = tid + t * 256;
        int k2 = u4 >> 5, n4 = u4 & 31;
        *(uint4*)&Ws2[k2][n4 * 4] = ((const uint4*)&g_w1bf[k2 * 128])[n4];
    }
#pragma unroll
    for (int t = 0; t < 4; t++) {
        int u4 = tid + t * 256;
        int r = u4 >> 4, c4 = u4 & 15;
        uint4 v = make_uint4(0u, 0u, 0u, 0u);
        if (row0 + r < N_NODES)
            v = ((const uint4*)&g_aggbf[(size_t)(row0 + r) * 64])[c4];
        *(uint4*)&As2[r][c4 * 4] = v;
    }
    __syncthreads();

    int wm = wid >> 1, wn = wid & 1;
    int g = lane >> 2, t4 = lane & 3;
    float acc[8][4];
#pragma unroll
    for (int t = 0; t < 8; t++)
#pragma unroll
        for (int j = 0; j < 4; j++) acc[t][j] = 0.f;

#pragma unroll
    for (int chunk = 0; chunk < 8; chunk++) {
        unsigned a0 = As2[wm * 16 + g][chunk * 8 + t4];
        unsigned a1 = As2[wm * 16 + g + 8][chunk * 8 + t4];
        unsigned a2 = As2[wm * 16 + g][chunk * 8 + t4 + 4];
        unsigned a3 = As2[wm * 16 + g + 8][chunk * 8 + t4 + 4];
#pragma unroll
        for (int tile = 0; tile < 8; tile++) {
            int n0 = wn * 64 + tile * 8;
            unsigned b0 = Ws2[chunk * 8 + t4][n0 + g];
            unsigned bb = Ws2[chunk * 8 + t4 + 4][n0 + g];
            mma_bf16(acc[tile], a0, a1, a2, a3, b0, bb);
        }
    }

    float tA0 = 0.f, tA1 = 0.f, tB0 = 0.f, tB1 = 0.f;
#pragma unroll
    for (int tile = 0; tile < 8; tile++) {
        int c0 = wn * 64 + tile * 8 + t4 * 2;
        float bias0 = b1s[c0], bias1 = b1s[c0 + 1];
        float h00 = fmaxf(acc[tile][0] + bias0, 0.f);
        float h01 = fmaxf(acc[tile][1] + bias1, 0.f);
        float h10 = fmaxf(acc[tile][2] + bias0, 0.f);
        float h11 = fmaxf(acc[tile][3] + bias1, 0.f);
        float w00 = W2s[c0 * 2 + 0], w01 = W2s[c0 * 2 + 1];
        float w10 = W2s[(c0 + 1) * 2 + 0], w11 = W2s[(c0 + 1) * 2 + 1];
        tA0 += h00 * w00 + h01 * w10;
        tA1 += h00 * w01 + h01 * w11;
        tB0 += h10 * w00 + h11 * w10;
        tB1 += h10 * w01 + h11 * w11;
    }
    tA0 += __shfl_xor_sync(0xffffffffu, tA0, 1); tA0 += __shfl_xor_sync(0xffffffffu, tA0, 2);
    tA1 += __shfl_xor_sync(0xffffffffu, tA1, 1); tA1 += __shfl_xor_sync(0xffffffffu, tA1, 2);
    tB0 += __shfl_xor_sync(0xffffffffu, tB0, 1); tB0 += __shfl_xor_sync(0xffffffffu, tB0, 2);
    tB1 += __shfl_xor_sync(0xffffffffu, tB1, 1); tB1 += __shfl_xor_sync(0xffffffffu, tB1, 2);
    if (t4 == 0) {
        int rlA = wm * 16 + g;
        int rlB = rlA + 8;
        tsh[wn][rlA][0] = tA0; tsh[wn][rlA][1] = tA1;
        tsh[wn][rlB][0] = tB0; tsh[wn][rlB][1] = tB1;
    }
    __syncthreads();
    if (tid < 128) {
        int rl = tid >> 1, c = tid & 1;
        int gr = row0 + rl;
        if (gr < N_NODES)
            g_t[gr * 2 + c] = tsh[0][rl][c] + tsh[1][rl][c];
    }
}

// layer-2 aggregation (CSR) + mean-pool; LAST BLOCK computes log-softmax out.
__global__ void k_agg2_pool(const float* __restrict__ b2, float* __restrict__ out) {
    __shared__ float sp[NG * NC];
    __shared__ float sc[NG];
    __shared__ int s_last;
    int tid = threadIdx.x;
    if (tid < NG * NC) sp[tid] = 0.f;
    if (tid < NG)      sc[tid] = 0.f;
    __syncthreads();
    int i = blockIdx.x * blockDim.x + tid;
    if (i < N_NODES) {
        int start = g_ptr[i];
        int deg = g_cnt_hist[i];
        float a0 = 0.f, a1 = 0.f;
        int j = 0;
        for (; j + 2 <= deg; j += 2) {
            uint2 e0 = g_epack[start + j];
            uint2 e1 = g_epack[start + j + 1];
            float w0 = __uint_as_float(e0.y), w1 = __uint_as_float(e1.y);
            float2 v0 = *(const float2*)&g_t[e0.x * 2];
            float2 v1 = *(const float2*)&g_t[e1.x * 2];
            a0 += w0 * v0.x + w1 * v1.x;
            a1 += w0 * v0.y + w1 * v1.y;
        }
        if (j < deg) {
            uint2 e0 = g_epack[start + j];
            float w0 = __uint_as_float(e0.y);
            float2 v0 = *(const float2*)&g_t[e0.x * 2];
            a0 += w0 * v0.x; a1 += w0 * v0.y;
        }
        float dc = g_dinv[i];
        a0 = a0 * dc + b2[0];
        a1 = a1 * dc + b2[1];
        int b = g_batch[i];
        atomicAdd(&sp[b * 2 + 0], a0);
        atomicAdd(&sp[b * 2 + 1], a1);
        atomicAdd(&sc[b], 1.f);
    }
    __syncthreads();
    if (tid < NG * NC && sp[tid] != 0.f) atomicAdd(&g_pool[tid], sp[tid]);
    if (tid < NG && sc[tid] != 0.f)      atomicAdd(&g_gcnt[tid], sc[tid]);

    // last-block ticket: the final block to pass here computes the output
    __threadfence();
    __syncthreads();
    if (tid == 0) s_last = (atomicAdd(&g_done, 1) == (int)gridDim.x - 1);
    __syncthreads();
    if (s_last && tid < NG) {
        int g = tid;
        float cnt = g_gcnt[g];
        float m = fmaxf(cnt, 1.0f);
        float p0 = g_pool[g * 2 + 0] / m;
        float p1 = g_pool[g * 2 + 1] / m;
        float mx = fmaxf(p0, p1);
        float lse = mx + logf(expf(p0 - mx) + expf(p1 - mx));
        out[g * 2 + 0] = p0 - lse;
        out[g * 2 + 1] = p1 - lse;
    }
}

// ---------------- launch ----------------
extern "C" void kernel_launch(void* const* d_in, const int* in_sizes, int n_in,
                              void* d_out, int out_size) {
    const float* x     = (const float*)d_in[0];
    const void*  ei    = d_in[1];
    const void*  batch = d_in[2];
    const float* W1    = (const float*)d_in[3];
    const float* b1    = (const float*)d_in[4];
    const float* W2    = (const float*)d_in[5];
    const float* b2    = (const float*)d_in[6];
    float* out = (float*)d_out;

    k_prep<<<((N_NODES * NH / 4) + 255) / 256, 256>>>(x, W1, (const unsigned int*)ei);
    k_build<<<(E_TOT + 255) / 256, 256>>>(ei);
    k_alloc<<<(N_NODES + 255) / 256, 256>>>(batch);
    k_fill<<<(E_TOT + 255) / 256, 256>>>(ei);
    k_agg1<<<(N_NODES * 32 + 255) / 256, 256>>>();
    k_gemm<<<(N_NODES + 63) / 64, 256>>>(b1, W2);
    k_agg2_pool<<<(N_NODES + 255) / 256, 256>>>(b2, out);
}